// round 11
// baseline (speedup 1.0000x reference)
#include <cuda_runtime.h>
#include <cuda_bf16.h>
#include <cuda_fp16.h>
#include <cstdint>
#include <math.h>

// Problem constants
#define BSZ   2
#define NQ    2048
#define NK    2048
#define DM    1024
#define AM    1024
#define NH    16
#define DHD   64
#define TOKQ  (BSZ*NQ)   // 4096
#define TOKK  (BSZ*NK)   // 4096
#define SIG_SCALE 0.35355339059327373f
#define EPSF  1e-5f
#define WSCALE 64.0f
#define WSI    (1.0f/64.0f)

// ---------------------------------------------------------------------------
// Scratch
// ---------------------------------------------------------------------------
__device__ uint8_t g_xq8 [TOKQ * DM];   // LN(query) e4m3
__device__ uint8_t g_kf8 [TOKK * DM];   // key feats e4m3
__device__ uint8_t g_Wq8 [AM * DM];     // weights e4m3 (x64)
__device__ uint8_t g_Wk8 [AM * DM];
__device__ uint8_t g_Wv8 [AM * DM];
__device__ uint8_t g_Wo8 [DM * AM];
__device__ __half  g_qh  [TOKQ * AM];   // f16 normed Q
__device__ __half  g_kh  [TOKK * AM];
__device__ __half  g_vh  [TOKK * AM];
__device__ __half  g_ctxh[TOKQ * AM];
__device__ uint8_t g_ctx8[TOKQ * AM];   // ctx e4m3 for Wo
__device__ __half  g_oh  [TOKQ * DM];

// ---------------------------------------------------------------------------
// Low-level helpers
// ---------------------------------------------------------------------------
__device__ __forceinline__ uint32_t smem_u32(const void* p) {
    uint32_t a;
    asm("{ .reg .u64 t; cvta.to.shared.u64 t, %1; cvt.u32.u64 %0, t; }"
        : "=r"(a) : "l"(p));
    return a;
}
__device__ __forceinline__ void cp_async16(uint32_t saddr, const void* gaddr) {
    asm volatile("cp.async.cg.shared.global [%0], [%1], 16;"
                 :: "r"(saddr), "l"(gaddr));
}
#define CP_COMMIT() asm volatile("cp.async.commit_group;" ::: "memory")
#define CP_WAIT(N)  asm volatile("cp.async.wait_group %0;" :: "n"(N) : "memory")

__device__ __forceinline__ void ldsm4(uint32_t& r0, uint32_t& r1,
                                      uint32_t& r2, uint32_t& r3, uint32_t a) {
    asm volatile("ldmatrix.sync.aligned.m8n8.x4.shared.b16 {%0,%1,%2,%3}, [%4];"
                 : "=r"(r0), "=r"(r1), "=r"(r2), "=r"(r3) : "r"(a));
}
__device__ __forceinline__ void ldsm4t(uint32_t& r0, uint32_t& r1,
                                       uint32_t& r2, uint32_t& r3, uint32_t a) {
    asm volatile("ldmatrix.sync.aligned.m8n8.x4.trans.shared.b16 {%0,%1,%2,%3}, [%4];"
                 : "=r"(r0), "=r"(r1), "=r"(r2), "=r"(r3) : "r"(a));
}
// f16 x f16 -> f16 accumulators
__device__ __forceinline__ void mma_h16(uint32_t* c, const uint32_t* a,
                                        uint32_t b0, uint32_t b1) {
    asm volatile(
        "mma.sync.aligned.m16n8k16.row.col.f16.f16.f16.f16 "
        "{%0,%1}, {%2,%3,%4,%5}, {%6,%7}, {%0,%1};"
        : "+r"(c[0]), "+r"(c[1])
        : "r"(a[0]), "r"(a[1]), "r"(a[2]), "r"(a[3]), "r"(b0), "r"(b1));
}
// e4m3 x e4m3 -> f32 accumulators (k32)
__device__ __forceinline__ void mma_f8(float* c, const uint32_t* a,
                                       uint32_t b0, uint32_t b1) {
    asm volatile(
        "mma.sync.aligned.m16n8k32.row.col.f32.e4m3.e4m3.f32 "
        "{%0,%1,%2,%3}, {%4,%5,%6,%7}, {%8,%9}, {%0,%1,%2,%3};"
        : "+f"(c[0]), "+f"(c[1]), "+f"(c[2]), "+f"(c[3])
        : "r"(a[0]), "r"(a[1]), "r"(a[2]), "r"(a[3]), "r"(b0), "r"(b1));
}

__device__ __forceinline__ uint32_t sig16x2(uint32_t s) {
    uint32_t u, t, r;
    asm("fma.rn.f16x2 %0, %1, %2, %3;"
        : "=r"(u) : "r"(s), "r"(0x38003800u), "r"(0xBE00BE00u)); // *0.5 - 1.5
    asm("tanh.approx.f16x2 %0, %1;" : "=r"(t) : "r"(u));
    asm("fma.rn.f16x2 %0, %1, %2, %2;" : "=r"(r) : "r"(t), "r"(0x38003800u));
    return r;
}
__device__ __forceinline__ void store2(__half* p, float a, float b) {
    uint32_t r;
    asm("cvt.rn.f16x2.f32 %0, %1, %2;" : "=r"(r) : "f"(b), "f"(a));
    *(uint32_t*)p = r;
}
// pack 4 floats -> 4 e4m3 bytes (little-endian order a,b,c,d)
__device__ __forceinline__ uint32_t pack4_e4m3(float a, float b, float c, float d) {
    uint16_t lo, hi;
    asm("cvt.rn.satfinite.e4m3x2.f32 %0, %1, %2;" : "=h"(lo) : "f"(b), "f"(a));
    asm("cvt.rn.satfinite.e4m3x2.f32 %0, %1, %2;" : "=h"(hi) : "f"(d), "f"(c));
    return (uint32_t)lo | ((uint32_t)hi << 16);
}

// ---------------------------------------------------------------------------
// FP8 GEMM mainloop: CTA 128x128, warp tile 32x64 (8 warps: 4m x 2n).
// e4m3 inputs K-major, f32 accum, K stage = 128 elements (128B rows, SW128),
// double-buffered cp.async (64 KB smem). acc[mi 0..1][n8 0..7][4]
// ---------------------------------------------------------------------------
#define GSM_STAGE 32768             // A 16KB + B 16KB
#define GSM_TOTAL (2 * GSM_STAGE)   // 64 KB

__device__ __forceinline__ void gemm_stage_load(
    uint32_t st, const uint8_t* Ag, const uint8_t* Bg, int K, int kt, int tid) {
    uint32_t sa = st, sb = st + 16384;
    #pragma unroll
    for (int s = 0; s < 4; s++) {
        int i = tid + s * 256;
        int row = i >> 3, cc = i & 7;
        uint32_t sw = (uint32_t)((cc ^ (row & 7)) << 4);
        cp_async16(sa + row * 128 + sw, Ag + (size_t)row * K + kt * 128 + cc * 16);
        cp_async16(sb + row * 128 + sw, Bg + (size_t)row * K + kt * 128 + cc * 16);
    }
}

__device__ __forceinline__ void gemm_mainloop_f8(
    const uint8_t* __restrict__ A, const uint8_t* __restrict__ B,
    int K, char* gsm, int bx, int by, float acc[2][8][4]) {
    uint32_t st[2] = { smem_u32(gsm), smem_u32(gsm) + GSM_STAGE };
    int tid = threadIdx.x, w = tid >> 5, lane = tid & 31;
    int wm = (w >> 1) * 32, wn = (w & 1) * 64;

    const uint8_t* Ag = A + (size_t)(by * 128) * K;
    const uint8_t* Bg = B + (size_t)(bx * 128) * K;
    const int NT = K / 128;   // 8

    #pragma unroll
    for (int i = 0; i < 2; i++)
        #pragma unroll
        for (int j = 0; j < 8; j++)
            #pragma unroll
            for (int r = 0; r < 4; r++) acc[i][j][r] = 0.f;

    gemm_stage_load(st[0], Ag, Bg, K, 0, tid);
    CP_COMMIT();

    for (int kt = 0; kt < NT; kt++) {
        if (kt + 1 < NT) {
            gemm_stage_load(st[(kt + 1) & 1], Ag, Bg, K, kt + 1, tid);
            CP_COMMIT();
            CP_WAIT(1);
        } else {
            CP_WAIT(0);
        }
        __syncthreads();

        uint32_t ab = st[kt & 1], bb = ab + 16384;
        #pragma unroll
        for (int ks = 0; ks < 4; ks++) {      // 4 x k32 per 128-elem stage
            uint32_t af[2][4];
            #pragma unroll
            for (int mi = 0; mi < 2; mi++) {
                int row = wm + mi * 16 + (lane & 15);
                int cc  = ks * 2 + (lane >> 4);
                ldsm4(af[mi][0], af[mi][1], af[mi][2], af[mi][3],
                      ab + row * 128 + ((cc ^ (row & 7)) << 4));
            }
            #pragma unroll
            for (int n16 = 0; n16 < 4; n16++) {
                int row = wn + n16 * 16 + (lane & 7) + ((lane >> 4) << 3);
                int cc  = ks * 2 + ((lane >> 3) & 1);
                uint32_t b0, b1, b2, b3;
                ldsm4(b0, b1, b2, b3, bb + row * 128 + ((cc ^ (row & 7)) << 4));
                #pragma unroll
                for (int mi = 0; mi < 2; mi++) {
                    mma_f8(acc[mi][n16 * 2 + 0], af[mi], b0, b1);
                    mma_f8(acc[mi][n16 * 2 + 1], af[mi], b2, b3);
                }
            }
        }
        __syncthreads();
    }
}

// ---------------------------------------------------------------------------
// QKV projection (fp8) with FUSED qk-norm (warp's 64 cols == one full head).
// blockIdx.z: 0=Q (qknorm), 1=K (kknorm), 2=V (plain, x WSI).
// Weights pre-scaled x64; LN scale-invariance means Q/K need no descale.
// ---------------------------------------------------------------------------
__global__ __launch_bounds__(256, 2)
void qkv_gemm_kernel(const uint8_t* __restrict__ xq,
                     const uint8_t* __restrict__ kf,
                     const uint8_t* __restrict__ Wq,
                     const uint8_t* __restrict__ Wk,
                     const uint8_t* __restrict__ Wv,
                     const float* __restrict__ qn_s,
                     const float* __restrict__ qn_b,
                     const float* __restrict__ kn_s,
                     const float* __restrict__ kn_b,
                     __half* __restrict__ qo,
                     __half* __restrict__ ko,
                     __half* __restrict__ vo) {
    extern __shared__ __align__(1024) char gsm[];
    int z = blockIdx.z;
    const uint8_t* A = (z == 0) ? xq : kf;
    const uint8_t* B = (z == 0) ? Wq : (z == 1) ? Wk : Wv;
    __half* C = (z == 0) ? qo : (z == 1) ? ko : vo;
    const float* sc = (z == 0) ? qn_s : kn_s;
    const float* bi = (z == 0) ? qn_b : kn_b;

    float acc[2][8][4];
    gemm_mainloop_f8(A, B, DM, gsm, blockIdx.x, blockIdx.y, acc);

    int tid = threadIdx.x, w = tid >> 5, lane = tid & 31;
    int wm = (w >> 1) * 32, wn = (w & 1) * 64;
    int crow0 = blockIdx.y * 128 + wm + (lane >> 2);
    int ccol0 = blockIdx.x * 128 + wn + (lane & 3) * 2;

    if (z == 2) {
        #pragma unroll
        for (int mi = 0; mi < 2; mi++) {
            #pragma unroll
            for (int nj = 0; nj < 8; nj++) {
                int row = crow0 + mi * 16;
                int col = ccol0 + nj * 8;
                store2(C + (size_t)row * AM + col,
                       acc[mi][nj][0] * WSI, acc[mi][nj][1] * WSI);
                store2(C + (size_t)(row + 8) * AM + col,
                       acc[mi][nj][2] * WSI, acc[mi][nj][3] * WSI);
            }
        }
        return;
    }

    // ---- fused qk-norm (LN over 64 head dims, scale-invariant to x64) ----
    #pragma unroll
    for (int mi = 0; mi < 2; mi++) {
        float slo = 0.f, qlo = 0.f, shi = 0.f, qhi = 0.f;
        #pragma unroll
        for (int nj = 0; nj < 8; nj++) {
            float v0 = acc[mi][nj][0], v1 = acc[mi][nj][1];
            float v2 = acc[mi][nj][2], v3 = acc[mi][nj][3];
            slo += v0 + v1; qlo += v0 * v0 + v1 * v1;
            shi += v2 + v3; qhi += v2 * v2 + v3 * v3;
        }
        #pragma unroll
        for (int o = 1; o <= 2; o <<= 1) {
            slo += __shfl_xor_sync(0xffffffffu, slo, o);
            qlo += __shfl_xor_sync(0xffffffffu, qlo, o);
            shi += __shfl_xor_sync(0xffffffffu, shi, o);
            qhi += __shfl_xor_sync(0xffffffffu, qhi, o);
        }
        float m0 = slo * (1.f / DHD);
        float m1 = shi * (1.f / DHD);
        // values are 64x true scale; eps effect negligible (var >> eps/4096)
        float r0 = rsqrtf(qlo * (1.f / DHD) - m0 * m0 + EPSF);
        float r1 = rsqrtf(qhi * (1.f / DHD) - m1 * m1 + EPSF);

        int row0 = crow0 + mi * 16;
        #pragma unroll
        for (int nj = 0; nj < 8; nj++) {
            int cih = nj * 8 + (lane & 3) * 2;
            float sc0 = sc[cih], sc1 = sc[cih + 1];
            float bi0 = bi[cih], bi1 = bi[cih + 1];
            int col = ccol0 + nj * 8;
            float a0 = ((acc[mi][nj][0] - m0) * r0 * sc0 + bi0) * SIG_SCALE;
            float a1 = ((acc[mi][nj][1] - m0) * r0 * sc1 + bi1) * SIG_SCALE;
            float a2 = ((acc[mi][nj][2] - m1) * r1 * sc0 + bi0) * SIG_SCALE;
            float a3 = ((acc[mi][nj][3] - m1) * r1 * sc1 + bi1) * SIG_SCALE;
            store2(C + (size_t)row0 * AM + col, a0, a1);
            store2(C + (size_t)(row0 + 8) * AM + col, a2, a3);
        }
    }
}

// Wo projection (fp8) -> f16, descaled by WSI
__global__ __launch_bounds__(256, 2)
void wo_gemm_kernel(const uint8_t* __restrict__ A,
                    const uint8_t* __restrict__ B,
                    __half* __restrict__ C) {
    extern __shared__ __align__(1024) char gsm[];
    float acc[2][8][4];
    gemm_mainloop_f8(A, B, AM, gsm, blockIdx.x, blockIdx.y, acc);
    int tid = threadIdx.x, w = tid >> 5, lane = tid & 31;
    int wm = (w >> 1) * 32, wn = (w & 1) * 64;
    int crow0 = blockIdx.y * 128 + wm + (lane >> 2);
    int ccol0 = blockIdx.x * 128 + wn + (lane & 3) * 2;
    #pragma unroll
    for (int mi = 0; mi < 2; mi++) {
        #pragma unroll
        for (int nj = 0; nj < 8; nj++) {
            int row = crow0 + mi * 16, col = ccol0 + nj * 8;
            store2(C + (size_t)row * DM + col,
                   acc[mi][nj][0] * WSI, acc[mi][nj][1] * WSI);
            store2(C + (size_t)(row + 8) * DM + col,
                   acc[mi][nj][2] * WSI, acc[mi][nj][3] * WSI);
        }
    }
}

// ---------------------------------------------------------------------------
// Fused sigmoid attention (round-9 best shape): q-tile 128, 8 warps each
// 16 q-rows x 64 keys; 128-key stages double-buffered (80 KB smem), f16.
// ---------------------------------------------------------------------------
#define ASM_Q    0
#define ASM_K(s) (16384 + (s) * 32768)
#define ASM_V(s) (16384 + (s) * 32768 + 16384)
#define ASM_TOTAL (16384 + 2 * 32768)          // 80 KB

__global__ __launch_bounds__(256, 2)
void attn_mma_kernel(const __half* __restrict__ Q,
                     const __half* __restrict__ Km,
                     const __half* __restrict__ V,
                     __half* __restrict__ O) {
    extern __shared__ __align__(1024) char asm_[];
    uint32_t sb = smem_u32(asm_);
    int tid = threadIdx.x, w = tid >> 5, lane = tid & 31;
    int q0 = blockIdx.x * 128, h = blockIdx.y, b = blockIdx.z;

    const __half* Qg = Q  + ((size_t)(b * NQ + q0)) * AM + h * DHD;
    const __half* Kg = Km + ((size_t)(b * NK)) * AM + h * DHD;
    const __half* Vg = V  + ((size_t)(b * NK)) * AM + h * DHD;

    #pragma unroll
    for (int s = 0; s < 4; s++) {
        int i = tid + s * 256;
        int row = i >> 3, cc = i & 7;
        cp_async16(sb + ASM_Q + row * 128 + ((cc ^ (row & 7)) << 4),
                   Qg + (size_t)row * AM + cc * 8);
    }
    #pragma unroll
    for (int s = 0; s < 4; s++) {
        int i = tid + s * 256;
        int row = i >> 3, cc = i & 7;
        uint32_t sw = (uint32_t)((cc ^ (row & 7)) << 4);
        cp_async16(sb + ASM_K(0) + row * 128 + sw, Kg + (size_t)row * AM + cc * 8);
        cp_async16(sb + ASM_V(0) + row * 128 + sw, Vg + (size_t)row * AM + cc * 8);
    }
    CP_COMMIT();

    uint32_t qf[4][4];
    uint32_t cacc[8][2];
    #pragma unroll
    for (int j = 0; j < 8; j++) { cacc[j][0] = 0u; cacc[j][1] = 0u; }

    const int NT = NK / 128;   // 16 stages
    for (int kt = 0; kt < NT; kt++) {
        int buf = kt & 1;
        if (kt + 1 < NT) {
            int nb = (kt + 1) & 1;
            const __half* Kg2 = Kg + (size_t)(kt + 1) * 128 * AM;
            const __half* Vg2 = Vg + (size_t)(kt + 1) * 128 * AM;
            #pragma unroll
            for (int s = 0; s < 4; s++) {
                int i = tid + s * 256;
                int row = i >> 3, cc = i & 7;
                uint32_t sw = (uint32_t)((cc ^ (row & 7)) << 4);
                cp_async16(sb + ASM_K(nb) + row * 128 + sw, Kg2 + (size_t)row * AM + cc * 8);
                cp_async16(sb + ASM_V(nb) + row * 128 + sw, Vg2 + (size_t)row * AM + cc * 8);
            }
            CP_COMMIT();
            CP_WAIT(1);
        } else {
            CP_WAIT(0);
        }
        __syncthreads();

        if (kt == 0) {
            #pragma unroll
            for (int ks = 0; ks < 4; ks++) {
                int row = w * 16 + (lane & 15);
                int cc  = ks * 2 + (lane >> 4);
                ldsm4(qf[ks][0], qf[ks][1], qf[ks][2], qf[ks][3],
                      sb + ASM_Q + row * 128 + ((cc ^ (row & 7)) << 4));
            }
        }

        #pragma unroll
        for (int sub = 0; sub < 2; sub++) {
            uint32_t kb = sb + ASM_K(buf) + sub * 8192;
            uint32_t vb = sb + ASM_V(buf) + sub * 8192;

            uint32_t sacc[8][2];
            #pragma unroll
            for (int j = 0; j < 8; j++) { sacc[j][0] = 0u; sacc[j][1] = 0u; }

            #pragma unroll
            for (int ks = 0; ks < 4; ks++) {
                #pragma unroll
                for (int njj = 0; njj < 4; njj++) {
                    int row = njj * 16 + (lane & 7) + ((lane >> 4) << 3);
                    int cc  = ks * 2 + ((lane >> 3) & 1);
                    uint32_t b0, b1, b2, b3;
                    ldsm4(b0, b1, b2, b3, kb + row * 128 + ((cc ^ (row & 7)) << 4));
                    mma_h16(sacc[njj * 2 + 0], qf[ks], b0, b1);
                    mma_h16(sacc[njj * 2 + 1], qf[ks], b2, b3);
                }
            }

            uint32_t pa[4][4];
            #pragma unroll
            for (int ks = 0; ks < 4; ks++) {
                pa[ks][0] = sig16x2(sacc[2 * ks + 0][0]);
                pa[ks][1] = sig16x2(sacc[2 * ks + 0][1]);
                pa[ks][2] = sig16x2(sacc[2 * ks + 1][0]);
                pa[ks][3] = sig16x2(sacc[2 * ks + 1][1]);
            }

            #pragma unroll
            for (int ks = 0; ks < 4; ks++) {
                #pragma unroll
                for (int djj = 0; djj < 4; djj++) {
                    int row = ks * 16 + (lane & 15);
                    int cc  = djj * 2 + (lane >> 4);
                    uint32_t v0, v1, v2, v3;
                    ldsm4t(v0, v1, v2, v3, vb + row * 128 + ((cc ^ (row & 7)) << 4));
                    mma_h16(cacc[djj * 2 + 0], pa[ks], v0, v1);
                    mma_h16(cacc[djj * 2 + 1], pa[ks], v2, v3);
                }
            }
        }
        __syncthreads();
    }

    __half* Ob = O + ((size_t)(b * NQ)) * AM + h * DHD;
    int r0 = q0 + w * 16 + (lane >> 2);
    #pragma unroll
    for (int j = 0; j < 8; j++) {
        int col = j * 8 + (lane & 3) * 2;
        *(uint32_t*)(Ob + (size_t)r0 * AM + col)       = cacc[j][0];
        *(uint32_t*)(Ob + (size_t)(r0 + 8) * AM + col) = cacc[j][1];
    }
}

// ---------------------------------------------------------------------------
// Elementwise / norm kernels
// ---------------------------------------------------------------------------
__device__ __forceinline__ float warp_sum(float v) {
    #pragma unroll
    for (int o = 16; o; o >>= 1) v += __shfl_xor_sync(0xffffffffu, v, o);
    return v;
}

// fp32 -> e4m3 with scale (n multiple of 1024)
__global__ void cvt_f2e_kernel(const float* __restrict__ x,
                               uint8_t* __restrict__ y, float scale) {
    int i = (blockIdx.x * blockDim.x + threadIdx.x) * 4;
    float4 v = *(const float4*)(x + i);
    *(uint32_t*)(y + i) = pack4_e4m3(v.x * scale, v.y * scale,
                                     v.z * scale, v.w * scale);
}

// f16 -> e4m3 (for ctx)
__global__ void cvt_h2e_kernel(const __half* __restrict__ x,
                               uint8_t* __restrict__ y) {
    int i = (blockIdx.x * blockDim.x + threadIdx.x) * 4;
    uint2 v = *(const uint2*)(x + i);
    float2 f0 = __half22float2(*(__half2*)&v.x);
    float2 f1 = __half22float2(*(__half2*)&v.y);
    *(uint32_t*)(y + i) = pack4_e4m3(f0.x, f0.y, f1.x, f1.y);
}

// LayerNorm rows of 1024, e4m3 output
__global__ void ln_rows_8_kernel(const float* __restrict__ x,
                                 const float* __restrict__ sc,
                                 const float* __restrict__ bi,
                                 uint8_t* __restrict__ y) {
    int row = blockIdx.x;
    const float* xr = x + (size_t)row * DM;
    uint8_t* yr = y + (size_t)row * DM;
    __shared__ float buf[DM];
    __shared__ float red[16];
    float s = 0.f, s2 = 0.f;
    for (int i = threadIdx.x; i < DM; i += 256) {
        float v = xr[i];
        buf[i] = v;
        s += v; s2 += v * v;
    }
    s = warp_sum(s); s2 = warp_sum(s2);
    int w = threadIdx.x >> 5, l = threadIdx.x & 31;
    if (l == 0) { red[w] = s; red[8 + w] = s2; }
    __syncthreads();
    if (threadIdx.x < 32) {
        float a  = (l < 8) ? red[l] : 0.f;
        float b2 = (l < 8) ? red[8 + l] : 0.f;
        a = warp_sum(a); b2 = warp_sum(b2);
        if (l == 0) { red[0] = a; red[1] = b2; }
    }
    __syncthreads();
    float mean = red[0] * (1.f / DM);
    float var  = red[1] * (1.f / DM) - mean * mean;
    float rs = rsqrtf(var + EPSF);
    int i4 = threadIdx.x * 4;   // 256*4 = 1024 = DM, single pass
    float a0 = (buf[i4 + 0] - mean) * rs * sc[i4 + 0] + bi[i4 + 0];
    float a1 = (buf[i4 + 1] - mean) * rs * sc[i4 + 1] + bi[i4 + 1];
    float a2 = (buf[i4 + 2] - mean) * rs * sc[i4 + 2] + bi[i4 + 2];
    float a3 = (buf[i4 + 3] - mean) * rs * sc[i4 + 3] + bi[i4 + 3];
    *(uint32_t*)(yr + i4) = pack4_e4m3(a0, a1, a2, a3);
}

__global__ void final_ln_kernel(const float* __restrict__ resid,
                                const __half* __restrict__ o,
                                const float* __restrict__ gamma,
                                const float* __restrict__ sc,
                                const float* __restrict__ bi,
                                float* __restrict__ out) {
    int row = blockIdx.x;
    const float* rr = resid + (size_t)row * DM;
    const __half* orow = o + (size_t)row * DM;
    float* yr = out + (size_t)row * DM;
    __shared__ float buf[DM];
    __shared__ float red[16];
    float s = 0.f, s2 = 0.f;
    for (int i = threadIdx.x; i < DM; i += 256) {
        float t = rr[i] + gamma[i] * __half2float(orow[i]);
        buf[i] = t;
        s += t; s2 += t * t;
    }
    s = warp_sum(s); s2 = warp_sum(s2);
    int w = threadIdx.x >> 5, l = threadIdx.x & 31;
    if (l == 0) { red[w] = s; red[8 + w] = s2; }
    __syncthreads();
    if (threadIdx.x < 32) {
        float a  = (l < 8) ? red[l] : 0.f;
        float b2 = (l < 8) ? red[8 + l] : 0.f;
        a = warp_sum(a); b2 = warp_sum(b2);
        if (l == 0) { red[0] = a; red[1] = b2; }
    }
    __syncthreads();
    float mean = red[0] * (1.f / DM);
    float var  = red[1] * (1.f / DM) - mean * mean;
    float rs = rsqrtf(var + EPSF);
    for (int i = threadIdx.x; i < DM; i += 256)
        yr[i] = (buf[i] - mean) * rs * sc[i] + bi[i];
}

// ---------------------------------------------------------------------------
// Launch
// ---------------------------------------------------------------------------
extern "C" void kernel_launch(void* const* d_in, const int* in_sizes, int n_in,
                              void* d_out, int out_size) {
    (void)in_sizes; (void)n_in; (void)out_size;
    const float* qf    = (const float*)d_in[0];
    const float* kf    = (const float*)d_in[1];
    const float* Wq    = (const float*)d_in[2];
    const float* Wk    = (const float*)d_in[3];
    const float* Wv    = (const float*)d_in[4];
    const float* Wo    = (const float*)d_in[5];
    const float* qn_s  = (const float*)d_in[6];
    const float* qn_b  = (const float*)d_in[7];
    const float* kn_s  = (const float*)d_in[8];
    const float* kn_b  = (const float*)d_in[9];
    const float* lq_s  = (const float*)d_in[10];
    const float* lq_b  = (const float*)d_in[11];
    const float* lo_s  = (const float*)d_in[12];
    const float* lo_b  = (const float*)d_in[13];
    const float* gamma = (const float*)d_in[14];
    float* out = (float*)d_out;

    uint8_t *xq8, *kf8, *Wq8, *Wk8, *Wv8, *Wo8, *ctx8;
    __half *qh, *kh, *vh, *ctxh, *oh;
    cudaGetSymbolAddress((void**)&xq8,  g_xq8);
    cudaGetSymbolAddress((void**)&kf8,  g_kf8);
    cudaGetSymbolAddress((void**)&Wq8,  g_Wq8);
    cudaGetSymbolAddress((void**)&Wk8,  g_Wk8);
    cudaGetSymbolAddress((void**)&Wv8,  g_Wv8);
    cudaGetSymbolAddress((void**)&Wo8,  g_Wo8);
    cudaGetSymbolAddress((void**)&ctx8, g_ctx8);
    cudaGetSymbolAddress((void**)&qh,   g_qh);
    cudaGetSymbolAddress((void**)&kh,   g_kh);
    cudaGetSymbolAddress((void**)&vh,   g_vh);
    cudaGetSymbolAddress((void**)&ctxh, g_ctxh);
    cudaGetSymbolAddress((void**)&oh,   g_oh);

    cudaFuncSetAttribute(qkv_gemm_kernel,
                         cudaFuncAttributeMaxDynamicSharedMemorySize, GSM_TOTAL);
    cudaFuncSetAttribute(wo_gemm_kernel,
                         cudaFuncAttributeMaxDynamicSharedMemorySize, GSM_TOTAL);
    cudaFuncSetAttribute(attn_mma_kernel,
                         cudaFuncAttributeMaxDynamicSharedMemorySize, ASM_TOTAL);

    const int WBLK = (AM * DM) / 1024;   // blocks per 1M-element matrix

    // 1) pre-LN on queries -> e4m3
    ln_rows_8_kernel<<<TOKQ, 256>>>(qf, lq_s, lq_b, xq8);
    // 2) key feats -> e4m3
    cvt_f2e_kernel<<<(TOKK * DM) / 1024, 256>>>(kf, kf8, 1.0f);
    // 3,4,5) weights -> e4m3 (x64)
    cvt_f2e_kernel<<<WBLK, 256>>>(Wq, Wq8, WSCALE);
    cvt_f2e_kernel<<<WBLK, 256>>>(Wk, Wk8, WSCALE);
    cvt_f2e_kernel<<<WBLK, 256>>>(Wv, Wv8, WSCALE);
    // 6) merged Q/K/V projections (fp8) with fused qk-norm  [profiled]
    qkv_gemm_kernel<<<dim3(AM / 128, TOKQ / 128, 3), 256, GSM_TOTAL>>>(
        xq8, kf8, Wq8, Wk8, Wv8, qn_s, qn_b, kn_s, kn_b, qh, kh, vh);
    // 7) fused sigmoid attention (f16)
    dim3 agrid(NQ / 128, NH, BSZ);
    attn_mma_kernel<<<agrid, 256, ASM_TOTAL>>>(qh, kh, vh, ctxh);
    // 8) Wo -> e4m3 (x64) ; ctx -> e4m3
    cvt_f2e_kernel<<<WBLK, 256>>>(Wo, Wo8, WSCALE);
    cvt_h2e_kernel<<<(TOKQ * AM) / 1024, 256>>>(ctxh, ctx8);
    // 9) output projection (fp8) -> f16
    wo_gemm_kernel<<<dim3(DM / 128, TOKQ / 128), 256, GSM_TOTAL>>>(ctx8, Wo8, oh);
    // 10) residual + gamma + post-LN
    final_ln_kernel<<<TOKQ, 256>>>(qf, oh, gamma, lo_s, lo_b, out);
}

// round 12
// speedup vs baseline: 1.0763x; 1.0763x over previous
#include <cuda_runtime.h>
#include <cuda_bf16.h>
#include <cuda_fp16.h>
#include <cstdint>
#include <math.h>

// Problem constants
#define BSZ   2
#define NQ    2048
#define NK    2048
#define DM    1024
#define AM    1024
#define NH    16
#define DHD   64
#define TOKQ  (BSZ*NQ)   // 4096
#define TOKK  (BSZ*NK)   // 4096
#define SIG_SCALE 0.35355339059327373f
#define EPSF  1e-5f

// ---------------------------------------------------------------------------
// Scratch
// ---------------------------------------------------------------------------
__device__ __half g_xqh [TOKQ * DM];
__device__ __half g_kfh [TOKK * DM];
__device__ __half g_Wqh [AM * DM];
__device__ __half g_Wkh [AM * DM];
__device__ __half g_Wvh [AM * DM];
__device__ __half g_Woh [DM * AM];
__device__ __half g_qh  [TOKQ * AM];
__device__ __half g_kh  [TOKK * AM];
__device__ __half g_vh  [TOKK * AM];
__device__ __half g_ctxh[TOKQ * AM];
__device__ __half g_oh  [TOKQ * DM];

// ---------------------------------------------------------------------------
// Low-level helpers
// ---------------------------------------------------------------------------
__device__ __forceinline__ uint32_t smem_u32(const void* p) {
    uint32_t a;
    asm("{ .reg .u64 t; cvta.to.shared.u64 t, %1; cvt.u32.u64 %0, t; }"
        : "=r"(a) : "l"(p));
    return a;
}
__device__ __forceinline__ void cp_async16(uint32_t saddr, const void* gaddr) {
    asm volatile("cp.async.cg.shared.global [%0], [%1], 16;"
                 :: "r"(saddr), "l"(gaddr));
}
#define CP_COMMIT() asm volatile("cp.async.commit_group;" ::: "memory")
#define CP_WAIT(N)  asm volatile("cp.async.wait_group %0;" :: "n"(N) : "memory")

__device__ __forceinline__ void ldsm4(uint32_t& r0, uint32_t& r1,
                                      uint32_t& r2, uint32_t& r3, uint32_t a) {
    asm volatile("ldmatrix.sync.aligned.m8n8.x4.shared.b16 {%0,%1,%2,%3}, [%4];"
                 : "=r"(r0), "=r"(r1), "=r"(r2), "=r"(r3) : "r"(a));
}
__device__ __forceinline__ void ldsm4t(uint32_t& r0, uint32_t& r1,
                                       uint32_t& r2, uint32_t& r3, uint32_t a) {
    asm volatile("ldmatrix.sync.aligned.m8n8.x4.trans.shared.b16 {%0,%1,%2,%3}, [%4];"
                 : "=r"(r0), "=r"(r1), "=r"(r2), "=r"(r3) : "r"(a));
}
__device__ __forceinline__ void mma_h16(uint32_t* c, const uint32_t* a,
                                        uint32_t b0, uint32_t b1) {
    asm volatile(
        "mma.sync.aligned.m16n8k16.row.col.f16.f16.f16.f16 "
        "{%0,%1}, {%2,%3,%4,%5}, {%6,%7}, {%0,%1};"
        : "+r"(c[0]), "+r"(c[1])
        : "r"(a[0]), "r"(a[1]), "r"(a[2]), "r"(a[3]), "r"(b0), "r"(b1));
}

__device__ __forceinline__ uint32_t sig16x2(uint32_t s) {
    uint32_t u, t, r;
    asm("fma.rn.f16x2 %0, %1, %2, %3;"
        : "=r"(u) : "r"(s), "r"(0x38003800u), "r"(0xBE00BE00u)); // *0.5 - 1.5
    asm("tanh.approx.f16x2 %0, %1;" : "=r"(t) : "r"(u));
    asm("fma.rn.f16x2 %0, %1, %2, %2;" : "=r"(r) : "r"(t), "r"(0x38003800u));
    return r;
}
__device__ __forceinline__ float2 h2f(uint32_t u) {
    __half2 h = *reinterpret_cast<__half2*>(&u);
    return __half22float2(h);
}
__device__ __forceinline__ void store2(__half* p, float a, float b) {
    uint32_t r;
    asm("cvt.rn.f16x2.f32 %0, %1, %2;" : "=r"(r) : "f"(b), "f"(a));
    *(uint32_t*)p = r;
}

// ---------------------------------------------------------------------------
// GEMM mainloop (round-10 best): CTA 128x128, warp tile 32x64 (8 warps 4m x 2n).
// f16 in/out/accum, K stage 64, double-buffered cp.async (64 KB smem), occ 3.
// ---------------------------------------------------------------------------
#define GSM_STAGE 32768             // A 16KB + B 16KB
#define GSM_TOTAL (2 * GSM_STAGE)   // 64 KB

__device__ __forceinline__ void gemm_stage_load(
    uint32_t st, const __half* Ag, const __half* Bg, int K, int kt, int tid) {
    uint32_t sa = st, sb = st + 16384;
    #pragma unroll
    for (int s = 0; s < 4; s++) {
        int i = tid + s * 256;
        int row = i >> 3, cc = i & 7;
        uint32_t sw = (uint32_t)((cc ^ (row & 7)) << 4);
        cp_async16(sa + row * 128 + sw, Ag + (size_t)row * K + kt * 64 + cc * 8);
        cp_async16(sb + row * 128 + sw, Bg + (size_t)row * K + kt * 64 + cc * 8);
    }
}

__device__ __forceinline__ void gemm_mainloop(
    const __half* __restrict__ A, const __half* __restrict__ B,
    int K, char* gsm, int bx, int by, uint32_t acc[2][8][2]) {
    uint32_t st[2] = { smem_u32(gsm), smem_u32(gsm) + GSM_STAGE };
    int tid = threadIdx.x, w = tid >> 5, lane = tid & 31;
    int wm = (w >> 1) * 32, wn = (w & 1) * 64;

    const __half* Ag = A + (size_t)(by * 128) * K;
    const __half* Bg = B + (size_t)(bx * 128) * K;
    const int NT = K / 64;

    #pragma unroll
    for (int i = 0; i < 2; i++)
        #pragma unroll
        for (int j = 0; j < 8; j++) { acc[i][j][0] = 0u; acc[i][j][1] = 0u; }

    gemm_stage_load(st[0], Ag, Bg, K, 0, tid);
    CP_COMMIT();

    for (int kt = 0; kt < NT; kt++) {
        if (kt + 1 < NT) {
            gemm_stage_load(st[(kt + 1) & 1], Ag, Bg, K, kt + 1, tid);
            CP_COMMIT();
            CP_WAIT(1);
        } else {
            CP_WAIT(0);
        }
        __syncthreads();

        uint32_t ab = st[kt & 1], bb = ab + 16384;
        #pragma unroll
        for (int ks = 0; ks < 4; ks++) {
            uint32_t af[2][4];
            #pragma unroll
            for (int mi = 0; mi < 2; mi++) {
                int row = wm + mi * 16 + (lane & 15);
                int cc  = ks * 2 + (lane >> 4);
                ldsm4(af[mi][0], af[mi][1], af[mi][2], af[mi][3],
                      ab + row * 128 + ((cc ^ (row & 7)) << 4));
            }
            #pragma unroll
            for (int n16 = 0; n16 < 4; n16++) {
                int row = wn + n16 * 16 + (lane & 7) + ((lane >> 4) << 3);
                int cc  = ks * 2 + ((lane >> 3) & 1);
                uint32_t b0, b1, b2, b3;
                ldsm4(b0, b1, b2, b3, bb + row * 128 + ((cc ^ (row & 7)) << 4));
                #pragma unroll
                for (int mi = 0; mi < 2; mi++) {
                    mma_h16(acc[mi][n16 * 2 + 0], af[mi], b0, b1);
                    mma_h16(acc[mi][n16 * 2 + 1], af[mi], b2, b3);
                }
            }
        }
        __syncthreads();
    }
}

// ---------------------------------------------------------------------------
// QKV projection with FUSED qk-norm (warp's 64 cols == one full head).
// blockIdx.z: 0=Q (qknorm), 1=K (kknorm), 2=V (plain).
// ---------------------------------------------------------------------------
__global__ __launch_bounds__(256, 3)
void qkv_gemm_kernel(const __half* __restrict__ xq,
                     const __half* __restrict__ kf,
                     const __half* __restrict__ Wq,
                     const __half* __restrict__ Wk,
                     const __half* __restrict__ Wv,
                     const float* __restrict__ qn_s,
                     const float* __restrict__ qn_b,
                     const float* __restrict__ kn_s,
                     const float* __restrict__ kn_b,
                     __half* __restrict__ qo,
                     __half* __restrict__ ko,
                     __half* __restrict__ vo) {
    extern __shared__ __align__(1024) char gsm[];
    int z = blockIdx.z;
    const __half* A = (z == 0) ? xq : kf;
    const __half* B = (z == 0) ? Wq : (z == 1) ? Wk : Wv;
    __half* C = (z == 0) ? qo : (z == 1) ? ko : vo;
    const float* sc = (z == 0) ? qn_s : kn_s;
    const float* bi = (z == 0) ? qn_b : kn_b;

    uint32_t acc[2][8][2];
    gemm_mainloop(A, B, DM, gsm, blockIdx.x, blockIdx.y, acc);

    int tid = threadIdx.x, w = tid >> 5, lane = tid & 31;
    int wm = (w >> 1) * 32, wn = (w & 1) * 64;
    int crow0 = blockIdx.y * 128 + wm + (lane >> 2);
    int ccol0 = blockIdx.x * 128 + wn + (lane & 3) * 2;

    if (z == 2) {
        #pragma unroll
        for (int mi = 0; mi < 2; mi++) {
            #pragma unroll
            for (int nj = 0; nj < 8; nj++) {
                int row = crow0 + mi * 16;
                int col = ccol0 + nj * 8;
                *(uint32_t*)(C + (size_t)row * AM + col)       = acc[mi][nj][0];
                *(uint32_t*)(C + (size_t)(row + 8) * AM + col) = acc[mi][nj][1];
            }
        }
        return;
    }

    // ---- fused qk-norm: warp's 64 cols = one full head; quad shuffle ----
    #pragma unroll
    for (int mi = 0; mi < 2; mi++) {
        float slo = 0.f, qlo = 0.f, shi = 0.f, qhi = 0.f;
        #pragma unroll
        for (int nj = 0; nj < 8; nj++) {
            float2 p0 = h2f(acc[mi][nj][0]);
            float2 p1 = h2f(acc[mi][nj][1]);
            slo += p0.x + p0.y; qlo += p0.x * p0.x + p0.y * p0.y;
            shi += p1.x + p1.y; qhi += p1.x * p1.x + p1.y * p1.y;
        }
        #pragma unroll
        for (int o = 1; o <= 2; o <<= 1) {
            slo += __shfl_xor_sync(0xffffffffu, slo, o);
            qlo += __shfl_xor_sync(0xffffffffu, qlo, o);
            shi += __shfl_xor_sync(0xffffffffu, shi, o);
            qhi += __shfl_xor_sync(0xffffffffu, qhi, o);
        }
        float m0 = slo * (1.f / DHD);
        float m1 = shi * (1.f / DHD);
        float r0 = rsqrtf(qlo * (1.f / DHD) - m0 * m0 + EPSF);
        float r1 = rsqrtf(qhi * (1.f / DHD) - m1 * m1 + EPSF);

        int row0 = crow0 + mi * 16;
        #pragma unroll
        for (int nj = 0; nj < 8; nj++) {
            int cih = nj * 8 + (lane & 3) * 2;
            float sc0 = sc[cih], sc1 = sc[cih + 1];
            float bi0 = bi[cih], bi1 = bi[cih + 1];
            int col = ccol0 + nj * 8;
            float2 p0 = h2f(acc[mi][nj][0]);
            float2 p1 = h2f(acc[mi][nj][1]);
            float a0 = ((p0.x - m0) * r0 * sc0 + bi0) * SIG_SCALE;
            float a1 = ((p0.y - m0) * r0 * sc1 + bi1) * SIG_SCALE;
            float a2 = ((p1.x - m1) * r1 * sc0 + bi0) * SIG_SCALE;
            float a3 = ((p1.y - m1) * r1 * sc1 + bi1) * SIG_SCALE;
            store2(C + (size_t)row0 * AM + col, a0, a1);
            store2(C + (size_t)(row0 + 8) * AM + col, a2, a3);
        }
    }
}

// Wo projection -> f16
__global__ __launch_bounds__(256, 3)
void wo_gemm_kernel(const __half* __restrict__ A,
                    const __half* __restrict__ B,
                    __half* __restrict__ C) {
    extern __shared__ __align__(1024) char gsm[];
    uint32_t acc[2][8][2];
    gemm_mainloop(A, B, AM, gsm, blockIdx.x, blockIdx.y, acc);
    int tid = threadIdx.x, w = tid >> 5, lane = tid & 31;
    int wm = (w >> 1) * 32, wn = (w & 1) * 64;
    int crow0 = blockIdx.y * 128 + wm + (lane >> 2);
    int ccol0 = blockIdx.x * 128 + wn + (lane & 3) * 2;
    #pragma unroll
    for (int mi = 0; mi < 2; mi++) {
        #pragma unroll
        for (int nj = 0; nj < 8; nj++) {
            int row = crow0 + mi * 16, col = ccol0 + nj * 8;
            *(uint32_t*)(C + (size_t)row * DM + col)       = acc[mi][nj][0];
            *(uint32_t*)(C + (size_t)(row + 8) * DM + col) = acc[mi][nj][1];
        }
    }
}

// ---------------------------------------------------------------------------
// Fused sigmoid attention (round-9 best): q-tile 128, 8 warps each
// 16 q-rows x 64 keys; 128-key stages double-buffered (80 KB smem), occ 2.
// ---------------------------------------------------------------------------
#define ASM_Q    0
#define ASM_K(s) (16384 + (s) * 32768)
#define ASM_V(s) (16384 + (s) * 32768 + 16384)
#define ASM_TOTAL (16384 + 2 * 32768)          // 80 KB

__global__ __launch_bounds__(256, 2)
void attn_mma_kernel(const __half* __restrict__ Q,
                     const __half* __restrict__ Km,
                     const __half* __restrict__ V,
                     __half* __restrict__ O) {
    extern __shared__ __align__(1024) char asm_[];
    uint32_t sb = smem_u32(asm_);
    int tid = threadIdx.x, w = tid >> 5, lane = tid & 31;
    int q0 = blockIdx.x * 128, h = blockIdx.y, b = blockIdx.z;

    const __half* Qg = Q  + ((size_t)(b * NQ + q0)) * AM + h * DHD;
    const __half* Kg = Km + ((size_t)(b * NK)) * AM + h * DHD;
    const __half* Vg = V  + ((size_t)(b * NK)) * AM + h * DHD;

    #pragma unroll
    for (int s = 0; s < 4; s++) {
        int i = tid + s * 256;
        int row = i >> 3, cc = i & 7;
        cp_async16(sb + ASM_Q + row * 128 + ((cc ^ (row & 7)) << 4),
                   Qg + (size_t)row * AM + cc * 8);
    }
    #pragma unroll
    for (int s = 0; s < 4; s++) {
        int i = tid + s * 256;
        int row = i >> 3, cc = i & 7;
        uint32_t sw = (uint32_t)((cc ^ (row & 7)) << 4);
        cp_async16(sb + ASM_K(0) + row * 128 + sw, Kg + (size_t)row * AM + cc * 8);
        cp_async16(sb + ASM_V(0) + row * 128 + sw, Vg + (size_t)row * AM + cc * 8);
    }
    CP_COMMIT();

    uint32_t qf[4][4];
    uint32_t cacc[8][2];
    #pragma unroll
    for (int j = 0; j < 8; j++) { cacc[j][0] = 0u; cacc[j][1] = 0u; }

    const int NT = NK / 128;   // 16 stages
    for (int kt = 0; kt < NT; kt++) {
        int buf = kt & 1;
        if (kt + 1 < NT) {
            int nb = (kt + 1) & 1;
            const __half* Kg2 = Kg + (size_t)(kt + 1) * 128 * AM;
            const __half* Vg2 = Vg + (size_t)(kt + 1) * 128 * AM;
            #pragma unroll
            for (int s = 0; s < 4; s++) {
                int i = tid + s * 256;
                int row = i >> 3, cc = i & 7;
                uint32_t sw = (uint32_t)((cc ^ (row & 7)) << 4);
                cp_async16(sb + ASM_K(nb) + row * 128 + sw, Kg2 + (size_t)row * AM + cc * 8);
                cp_async16(sb + ASM_V(nb) + row * 128 + sw, Vg2 + (size_t)row * AM + cc * 8);
            }
            CP_COMMIT();
            CP_WAIT(1);
        } else {
            CP_WAIT(0);
        }
        __syncthreads();

        if (kt == 0) {
            #pragma unroll
            for (int ks = 0; ks < 4; ks++) {
                int row = w * 16 + (lane & 15);
                int cc  = ks * 2 + (lane >> 4);
                ldsm4(qf[ks][0], qf[ks][1], qf[ks][2], qf[ks][3],
                      sb + ASM_Q + row * 128 + ((cc ^ (row & 7)) << 4));
            }
        }

        #pragma unroll
        for (int sub = 0; sub < 2; sub++) {
            uint32_t kb = sb + ASM_K(buf) + sub * 8192;
            uint32_t vb = sb + ASM_V(buf) + sub * 8192;

            uint32_t sacc[8][2];
            #pragma unroll
            for (int j = 0; j < 8; j++) { sacc[j][0] = 0u; sacc[j][1] = 0u; }

            #pragma unroll
            for (int ks = 0; ks < 4; ks++) {
                #pragma unroll
                for (int njj = 0; njj < 4; njj++) {
                    int row = njj * 16 + (lane & 7) + ((lane >> 4) << 3);
                    int cc  = ks * 2 + ((lane >> 3) & 1);
                    uint32_t b0, b1, b2, b3;
                    ldsm4(b0, b1, b2, b3, kb + row * 128 + ((cc ^ (row & 7)) << 4));
                    mma_h16(sacc[njj * 2 + 0], qf[ks], b0, b1);
                    mma_h16(sacc[njj * 2 + 1], qf[ks], b2, b3);
                }
            }

            uint32_t pa[4][4];
            #pragma unroll
            for (int ks = 0; ks < 4; ks++) {
                pa[ks][0] = sig16x2(sacc[2 * ks + 0][0]);
                pa[ks][1] = sig16x2(sacc[2 * ks + 0][1]);
                pa[ks][2] = sig16x2(sacc[2 * ks + 1][0]);
                pa[ks][3] = sig16x2(sacc[2 * ks + 1][1]);
            }

            #pragma unroll
            for (int ks = 0; ks < 4; ks++) {
                #pragma unroll
                for (int djj = 0; djj < 4; djj++) {
                    int row = ks * 16 + (lane & 15);
                    int cc  = djj * 2 + (lane >> 4);
                    uint32_t v0, v1, v2, v3;
                    ldsm4t(v0, v1, v2, v3, vb + row * 128 + ((cc ^ (row & 7)) << 4));
                    mma_h16(cacc[djj * 2 + 0], pa[ks], v0, v1);
                    mma_h16(cacc[djj * 2 + 1], pa[ks], v2, v3);
                }
            }
        }
        __syncthreads();
    }

    __half* Ob = O + ((size_t)(b * NQ)) * AM + h * DHD;
    int r0 = q0 + w * 16 + (lane >> 2);
    #pragma unroll
    for (int j = 0; j < 8; j++) {
        int col = j * 8 + (lane & 3) * 2;
        *(uint32_t*)(Ob + (size_t)r0 * AM + col)       = cacc[j][0];
        *(uint32_t*)(Ob + (size_t)(r0 + 8) * AM + col) = cacc[j][1];
    }
}

// ---------------------------------------------------------------------------
// Fused prep: one launch does LN(query)->f16, cvt(kf)->f16, cvt(4 weights)->f16.
// blocks [0,4096): LN rows; [4096,8192): kf; [8192,12288): weights.
// ---------------------------------------------------------------------------
__device__ __forceinline__ float warp_sum(float v) {
    #pragma unroll
    for (int o = 16; o; o >>= 1) v += __shfl_xor_sync(0xffffffffu, v, o);
    return v;
}

__global__ void prep_kernel(const float* __restrict__ qf,
                            const float* __restrict__ kf,
                            const float* __restrict__ Wq,
                            const float* __restrict__ Wk,
                            const float* __restrict__ Wv,
                            const float* __restrict__ Wo,
                            const float* __restrict__ lq_s,
                            const float* __restrict__ lq_b,
                            __half* __restrict__ xqh,
                            __half* __restrict__ kfh,
                            __half* __restrict__ Wqh,
                            __half* __restrict__ Wkh,
                            __half* __restrict__ Wvh,
                            __half* __restrict__ Woh) {
    int bidx = blockIdx.x;
    if (bidx >= TOKQ) {
        // conversion blocks: 1024 elems per block
        const float* src;
        __half* dst;
        int j = bidx - TOKQ;
        if (j < 4096) {                       // kf: 4M elems
            size_t off = (size_t)j * 1024;
            src = kf + off; dst = kfh + off;
        } else {
            j -= 4096;
            int wsel = j >> 10;               // 1024 blocks per 1M matrix
            size_t off = (size_t)(j & 1023) * 1024;
            if      (wsel == 0) { src = Wq + off; dst = Wqh + off; }
            else if (wsel == 1) { src = Wk + off; dst = Wkh + off; }
            else if (wsel == 2) { src = Wv + off; dst = Wvh + off; }
            else                { src = Wo + off; dst = Woh + off; }
        }
        int i = threadIdx.x * 4;
        float4 v = *(const float4*)(src + i);
        store2(dst + i,     v.x, v.y);
        store2(dst + i + 2, v.z, v.w);
        return;
    }

    // LN row
    int row = bidx;
    const float* xr = qf + (size_t)row * DM;
    __half* yr = xqh + (size_t)row * DM;
    __shared__ float buf[DM];
    __shared__ float red[16];
    float s = 0.f, s2 = 0.f;
    for (int i = threadIdx.x; i < DM; i += 256) {
        float v = xr[i];
        buf[i] = v;
        s += v; s2 += v * v;
    }
    s = warp_sum(s); s2 = warp_sum(s2);
    int w = threadIdx.x >> 5, l = threadIdx.x & 31;
    if (l == 0) { red[w] = s; red[8 + w] = s2; }
    __syncthreads();
    if (threadIdx.x < 32) {
        float a  = (l < 8) ? red[l] : 0.f;
        float b2 = (l < 8) ? red[8 + l] : 0.f;
        a = warp_sum(a); b2 = warp_sum(b2);
        if (l == 0) { red[0] = a; red[1] = b2; }
    }
    __syncthreads();
    float mean = red[0] * (1.f / DM);
    float var  = red[1] * (1.f / DM) - mean * mean;
    float rs = rsqrtf(var + EPSF);
    for (int i = threadIdx.x; i < DM; i += 256)
        yr[i] = __float2half((buf[i] - mean) * rs * lq_s[i] + lq_b[i]);
}

__global__ void final_ln_kernel(const float* __restrict__ resid,
                                const __half* __restrict__ o,
                                const float* __restrict__ gamma,
                                const float* __restrict__ sc,
                                const float* __restrict__ bi,
                                float* __restrict__ out) {
    int row = blockIdx.x;
    const float* rr = resid + (size_t)row * DM;
    const __half* orow = o + (size_t)row * DM;
    float* yr = out + (size_t)row * DM;
    __shared__ float buf[DM];
    __shared__ float red[16];
    float s = 0.f, s2 = 0.f;
    for (int i = threadIdx.x; i < DM; i += 256) {
        float t = rr[i] + gamma[i] * __half2float(orow[i]);
        buf[i] = t;
        s += t; s2 += t * t;
    }
    s = warp_sum(s); s2 = warp_sum(s2);
    int w = threadIdx.x >> 5, l = threadIdx.x & 31;
    if (l == 0) { red[w] = s; red[8 + w] = s2; }
    __syncthreads();
    if (threadIdx.x < 32) {
        float a  = (l < 8) ? red[l] : 0.f;
        float b2 = (l < 8) ? red[8 + l] : 0.f;
        a = warp_sum(a); b2 = warp_sum(b2);
        if (l == 0) { red[0] = a; red[1] = b2; }
    }
    __syncthreads();
    float mean = red[0] * (1.f / DM);
    float var  = red[1] * (1.f / DM) - mean * mean;
    float rs = rsqrtf(var + EPSF);
    for (int i = threadIdx.x; i < DM; i += 256)
        yr[i] = (buf[i] - mean) * rs * sc[i] + bi[i];
}

// ---------------------------------------------------------------------------
// Launch
// ---------------------------------------------------------------------------
extern "C" void kernel_launch(void* const* d_in, const int* in_sizes, int n_in,
                              void* d_out, int out_size) {
    (void)in_sizes; (void)n_in; (void)out_size;
    const float* qf    = (const float*)d_in[0];
    const float* kf    = (const float*)d_in[1];
    const float* Wq    = (const float*)d_in[2];
    const float* Wk    = (const float*)d_in[3];
    const float* Wv    = (const float*)d_in[4];
    const float* Wo    = (const float*)d_in[5];
    const float* qn_s  = (const float*)d_in[6];
    const float* qn_b  = (const float*)d_in[7];
    const float* kn_s  = (const float*)d_in[8];
    const float* kn_b  = (const float*)d_in[9];
    const float* lq_s  = (const float*)d_in[10];
    const float* lq_b  = (const float*)d_in[11];
    const float* lo_s  = (const float*)d_in[12];
    const float* lo_b  = (const float*)d_in[13];
    const float* gamma = (const float*)d_in[14];
    float* out = (float*)d_out;

    __half *xqh, *kfh, *Wqh, *Wkh, *Wvh, *Woh, *qh, *kh, *vh, *ctxh, *oh;
    cudaGetSymbolAddress((void**)&xqh,  g_xqh);
    cudaGetSymbolAddress((void**)&kfh,  g_kfh);
    cudaGetSymbolAddress((void**)&Wqh,  g_Wqh);
    cudaGetSymbolAddress((void**)&Wkh,  g_Wkh);
    cudaGetSymbolAddress((void**)&Wvh,  g_Wvh);
    cudaGetSymbolAddress((void**)&Woh,  g_Woh);
    cudaGetSymbolAddress((void**)&qh,   g_qh);
    cudaGetSymbolAddress((void**)&kh,   g_kh);
    cudaGetSymbolAddress((void**)&vh,   g_vh);
    cudaGetSymbolAddress((void**)&ctxh, g_ctxh);
    cudaGetSymbolAddress((void**)&oh,   g_oh);

    cudaFuncSetAttribute(qkv_gemm_kernel,
                         cudaFuncAttributeMaxDynamicSharedMemorySize, GSM_TOTAL);
    cudaFuncSetAttribute(wo_gemm_kernel,
                         cudaFuncAttributeMaxDynamicSharedMemorySize, GSM_TOTAL);
    cudaFuncSetAttribute(attn_mma_kernel,
                         cudaFuncAttributeMaxDynamicSharedMemorySize, ASM_TOTAL);

    // 1) fused prep: LN(query) + all fp32->f16 conversions
    prep_kernel<<<TOKQ + 4096 + 4096, 256>>>(
        qf, kf, Wq, Wk, Wv, Wo, lq_s, lq_b,
        xqh, kfh, Wqh, Wkh, Wvh, Woh);
    // 2) merged Q/K/V projections with fused qk-norm
    qkv_gemm_kernel<<<dim3(AM / 128, TOKQ / 128, 3), 256, GSM_TOTAL>>>(
        xqh, kfh, Wqh, Wkh, Wvh, qn_s, qn_b, kn_s, kn_b, qh, kh, vh);
    // 3) fused sigmoid attention
    dim3 agrid(NQ / 128, NH, BSZ);
    attn_mma_kernel<<<agrid, 256, ASM_TOTAL>>>(qh, kh, vh, ctxh);
    // 4) output projection -> f16
    wo_gemm_kernel<<<dim3(DM / 128, TOKQ / 128), 256, GSM_TOTAL>>>(ctxh, Woh, oh);
    // 5) residual + gamma + post-LN
    final_ln_kernel<<<TOKQ, 256>>>(qf, oh, gamma, lo_s, lo_b, out);
}